// round 17
// baseline (speedup 1.0000x reference)
#include <cuda_runtime.h>
#include <cuda_bf16.h>
#include <cstdint>

// Problem constants
#define BB    2048     // batch
#define KHIST 200      // history length
#define DD    512      // latent dim
#define HHID  1024     // 2*D
#define CBK   2048     // codebook size
#define BD    (BB*DD)  // 1048576
#define TH    50000    // item-id threshold: pass A < TH, pass B >= TH
#define SPLK  4        // split-K factor for gemm1

// ---------------- scratch (device globals; no allocation allowed) ----------
__device__ float        g_part[SPLK * BB * DD];  // split-K partials (16 MB)
__device__ float2       g_cn2[CBK];              // (cnorm_j, |c_j|)
__device__ float        g_bsum[BB];
__device__ int          g_count;                 // zero-init; self-resetting
__device__ float        g_macc[BB * DD];         // fp32 partial mean acc (pass A)
__device__ int          g_mcnt[BB];              // partial counts (pass A)

// bf16 hi/lo split operands
__device__ __nv_bfloat16 g_meanH[BB * DD],   g_meanL[BB * DD];
__device__ __nv_bfloat16 g_hidH [BB * HHID], g_hidL [BB * HHID];
__device__ __nv_bfloat16 g_W1tH [HHID * DD], g_W1tL [HHID * DD];
__device__ __nv_bfloat16 g_W2tH [DD * HHID], g_W2tL [DD * HHID];

// ---------------------------------------------------------------------------
// Portable PTX helpers (sm_80+; ptxas targets plain sm_103 — no tcgen05)
// ---------------------------------------------------------------------------
__device__ __forceinline__ uint32_t smem_u32(const void* p) {
    uint32_t a;
    asm("{ .reg .u64 t; cvta.to.shared.u64 t, %1; cvt.u32.u64 %0, t; }" : "=r"(a) : "l"(p));
    return a;
}

#define CP_ASYNC16(dst, src) \
    asm volatile("cp.async.cg.shared.global [%0], [%1], 16;" :: "r"(dst), "l"(src))
#define CP_COMMIT() asm volatile("cp.async.commit_group;" ::: "memory")
#define CP_WAIT0()  asm volatile("cp.async.wait_group 0;" ::: "memory")
#define CP_WAIT1()  asm volatile("cp.async.wait_group 1;" ::: "memory")

__device__ __forceinline__ void ldsm4(uint32_t (&r)[4], uint32_t addr) {
    asm volatile("ldmatrix.sync.aligned.m8n8.x4.shared.b16 {%0,%1,%2,%3}, [%4];"
                 : "=r"(r[0]), "=r"(r[1]), "=r"(r[2]), "=r"(r[3]) : "r"(addr));
}

__device__ __forceinline__ void mma16816(float (&d)[4], const uint32_t (&a)[4],
                                         uint32_t b0, uint32_t b1) {
    asm volatile(
        "mma.sync.aligned.m16n8k16.row.col.f32.bf16.bf16.f32 "
        "{%0,%1,%2,%3}, {%4,%5,%6,%7}, {%8,%9}, {%0,%1,%2,%3};"
        : "+f"(d[0]), "+f"(d[1]), "+f"(d[2]), "+f"(d[3])
        : "r"(a[0]), "r"(a[1]), "r"(a[2]), "r"(a[3]), "r"(b0), "r"(b1));
}

__device__ __forceinline__ void split_bf16(float v, __nv_bfloat16& h, __nv_bfloat16& l) {
    h = __float2bfloat16(v);
    l = __float2bfloat16(v - __bfloat162float(h));
}

// ---------------------------------------------------------------------------
// PREP pass A (5120 blocks x 128 thr):
//   blocks [0,2048)    : gather items in (0, TH) -> fp32 partial acc + count
//   blocks [2048,4096) : codebook norms -> (cnorm, |c|)
//   blocks [4096,4608) : W1^T hi/lo split
//   blocks [4608,5120) : W2^T hi/lo split
// ---------------------------------------------------------------------------
__global__ void __launch_bounds__(128) prepA_kernel(
    const int* __restrict__ items, const float* __restrict__ item_embed,
    const float* __restrict__ codebook,
    const float* __restrict__ W1, const float* __restrict__ W2)
{
    __shared__ int   sidx[KHIST];
    __shared__ float ts[32][33];
    __shared__ float red[4];

    const int blk = blockIdx.x;
    const int t = threadIdx.x;

    if (blk < 2048) {
        int b = blk;
        for (int i = t; i < KHIST; i += 128) sidx[i] = items[b * KHIST + i];
        __syncthreads();
        const float4* E4 = (const float4*)item_embed;
        float4 acc = make_float4(0.f, 0.f, 0.f, 0.f);
        int cnt = 0;
        #pragma unroll 4
        for (int k = 0; k < KHIST; k++) {
            int idx = sidx[k];
            if (idx != 0 && idx < TH) {       // uniform across the block
                float4 v = E4[(size_t)idx * 128 + t];
                acc.x += v.x; acc.y += v.y; acc.z += v.z; acc.w += v.w;
                cnt++;
            }
        }
        ((float4*)g_macc)[(size_t)b * 128 + t] = acc;
        if (t == 0) g_mcnt[b] = cnt;
    } else if (blk < 4096) {
        int j = blk - 2048;
        float4 v = ((const float4*)codebook)[j * 128 + t];
        float s = v.x * v.x + v.y * v.y + v.z * v.z + v.w * v.w;
        #pragma unroll
        for (int o = 16; o > 0; o >>= 1) s += __shfl_down_sync(0xffffffffu, s, o);
        if ((t & 31) == 0) red[t >> 5] = s;
        __syncthreads();
        if (t == 0) {
            float cn = red[0] + red[1] + red[2] + red[3];
            g_cn2[j] = make_float2(cn, sqrtf(cn));
        }
    } else {
        const float* W;
        __nv_bfloat16 *WtH, *WtL;
        int KD, ND, w;
        if (blk < 4608) {
            w = blk - 4096; W = W1; WtH = g_W1tH; WtL = g_W1tL; KD = DD; ND = HHID;
        } else {
            w = blk - 4608; W = W2; WtH = g_W2tH; WtL = g_W2tL; KD = HHID; ND = DD;
        }
        int nblk = ND / 32;
        int n0 = (w % nblk) * 32, k0 = (w / nblk) * 32;
        int tx = t & 31, ty = t >> 5;
        #pragma unroll
        for (int i = ty; i < 32; i += 4)
            ts[i][tx] = W[(size_t)(k0 + i) * ND + n0 + tx];
        __syncthreads();
        #pragma unroll
        for (int i = ty; i < 32; i += 4) {
            float v = ts[tx][i];
            __nv_bfloat16 h, l;
            split_bf16(v, h, l);
            size_t o = (size_t)(n0 + i) * KD + k0 + tx;
            WtH[o] = h;
            WtL[o] = l;
        }
    }
}

// ---------------------------------------------------------------------------
// PREP pass B (2048 blocks x 128 thr): gather items >= TH, combine with
// pass-A partials, finalize mean, bf16 hi/lo split.
// ---------------------------------------------------------------------------
__global__ void __launch_bounds__(128) prepB_kernel(
    const int* __restrict__ items, const float* __restrict__ item_embed)
{
    __shared__ int sidx[KHIST];
    const int b = blockIdx.x;
    const int t = threadIdx.x;
    for (int i = t; i < KHIST; i += 128) sidx[i] = items[b * KHIST + i];
    __syncthreads();

    const float4* E4 = (const float4*)item_embed;
    float4 acc = ((const float4*)g_macc)[(size_t)b * 128 + t];
    int cnt = g_mcnt[b];
    #pragma unroll 4
    for (int k = 0; k < KHIST; k++) {
        int idx = sidx[k];
        if (idx >= TH) {                      // uniform across the block
            float4 v = E4[(size_t)idx * 128 + t];
            acc.x += v.x; acc.y += v.y; acc.z += v.z; acc.w += v.w;
            cnt++;
        }
    }
    float inv = 1.0f / (float)cnt;
    float vals[4] = {acc.x * inv, acc.y * inv, acc.z * inv, acc.w * inv};
    size_t base = (size_t)b * DD + t * 4;
    __nv_bfloat16 h[4], l[4];
    #pragma unroll
    for (int i = 0; i < 4; i++) split_bf16(vals[i], h[i], l[i]);
    *(__nv_bfloat162*)&g_meanH[base]     = {h[0], h[1]};
    *(__nv_bfloat162*)&g_meanH[base + 2] = {h[2], h[3]};
    *(__nv_bfloat162*)&g_meanL[base]     = {l[0], l[1]};
    *(__nv_bfloat162*)&g_meanL[base + 2] = {l[2], l[3]};
}

// ---------------------------------------------------------------------------
// Tensor-core GEMM (mma.sync bf16x3, fp32 accum): C = A[M,*] @ B[N,*]^T over
// K range [blockIdx.z*Kd, (blockIdx.z+1)*Kd), row stride ldK. 2-stage cp.async.
// WHICH=0: hid = relu(mean @ W1t^T + b1) -> bf16 hi/lo   grid(16,16,1)
// WHICH=1: split-K partials of hid @ W2t^T -> g_part     grid(8,16,SPLK)
// ---------------------------------------------------------------------------
template<int BM, int WHICH>
__global__ void __launch_bounds__(256, 2) gemm_mma(
    const __nv_bfloat16* __restrict__ Ah, const __nv_bfloat16* __restrict__ Al,
    const __nv_bfloat16* __restrict__ Bh, const __nv_bfloat16* __restrict__ Bl,
    const float* __restrict__ bias, float* __restrict__ pout,
    int N, int Kd, int ldK)
{
    constexpr int BN  = 64;
    constexpr int WM  = BM / 4;
    constexpr int MT  = WM / 16;
    constexpr int STAGE = 2 * (BM + BN) * 128;

    extern __shared__ char smem[];
    const uint32_t sbase = smem_u32(smem);
    const int tid  = threadIdx.x;
    const int lane = tid & 31;
    const int w    = tid >> 5;
    const int warp_m0 = (w >> 1) * WM;
    const int warp_n0 = (w & 1) * 32;
    const int bm = blockIdx.y * BM, bn = blockIdx.x * BN;
    const int kb = blockIdx.z * Kd;           // split-K base offset

    auto loadT = [&](const __nv_bfloat16* __restrict__ src, int row0, int k0,
                     uint32_t dst, int R) {
        #pragma unroll 4
        for (int i = 0; i < R * 8; i += 256) {
            int u = tid + i;
            int r = u >> 3, c8 = u & 7;
            uint32_t sd = dst + r * 128 + ((c8 * 16) ^ ((r & 7) << 4));
            const __nv_bfloat16* gs = src + (size_t)(row0 + r) * ldK + kb + k0 + c8 * 8;
            CP_ASYNC16(sd, gs);
        }
    };
    auto issue = [&](int c, int buf) {
        uint32_t sb = sbase + (uint32_t)buf * STAGE;
        int k0 = c * 64;
        loadT(Ah, bm, k0, sb, BM);
        loadT(Al, bm, k0, sb + BM * 128, BM);
        loadT(Bh, bn, k0, sb + 2 * BM * 128, BN);
        loadT(Bl, bn, k0, sb + 2 * BM * 128 + BN * 128, BN);
    };

    const int tile = lane >> 3, lr = lane & 7;
    const uint32_t xorp = (uint32_t)(lr << 4);
    const int aRow = warp_m0 + ((tile & 1) << 3) + lr;
    const uint32_t aK = (uint32_t)((tile >> 1) << 4);
    const int bRow = warp_n0 + ((tile >> 1) << 3) + lr;
    const uint32_t bK = (uint32_t)((tile & 1) << 4);

    float acc[MT][4][4] = {};

    const int NC = Kd / 64;
    issue(0, 0); CP_COMMIT();
    issue(1, 1); CP_COMMIT();
    CP_WAIT1();
    __syncthreads();

    for (int c = 0; c < NC; c++) {
        uint32_t s0 = sbase + (uint32_t)(c & 1) * STAGE;
        uint32_t pA[2] = { s0, s0 + BM * 128 };
        uint32_t pB[2] = { s0 + 2 * BM * 128, s0 + 2 * BM * 128 + BN * 128 };

        #pragma unroll
        for (int kk = 0; kk < 4; kk++) {
            uint32_t akb = (((uint32_t)kk << 5) + aK) ^ xorp;
            uint32_t bkb = (((uint32_t)kk << 5) + bK) ^ xorp;
            uint32_t a[2][MT][4];
            uint32_t b[2][4][2];
            #pragma unroll
            for (int s = 0; s < 2; s++)
                #pragma unroll
                for (int mt = 0; mt < MT; mt++)
                    ldsm4(a[s][mt], pA[s] + (uint32_t)(aRow + mt * 16) * 128 + akb);
            #pragma unroll
            for (int s = 0; s < 2; s++)
                #pragma unroll
                for (int ng = 0; ng < 2; ng++) {
                    uint32_t t4[4];
                    ldsm4(t4, pB[s] + (uint32_t)(bRow + ng * 16) * 128 + bkb);
                    b[s][2 * ng][0] = t4[0]; b[s][2 * ng][1] = t4[1];
                    b[s][2 * ng + 1][0] = t4[2]; b[s][2 * ng + 1][1] = t4[3];
                }
            #pragma unroll
            for (int mt = 0; mt < MT; mt++)
                #pragma unroll
                for (int nt = 0; nt < 4; nt++)
                    mma16816(acc[mt][nt], a[0][mt], b[0][nt][0], b[0][nt][1]);
            #pragma unroll
            for (int mt = 0; mt < MT; mt++)
                #pragma unroll
                for (int nt = 0; nt < 4; nt++)
                    mma16816(acc[mt][nt], a[0][mt], b[1][nt][0], b[1][nt][1]);
            #pragma unroll
            for (int mt = 0; mt < MT; mt++)
                #pragma unroll
                for (int nt = 0; nt < 4; nt++)
                    mma16816(acc[mt][nt], a[1][mt], b[0][nt][0], b[0][nt][1]);
        }

        if (c == NC - 1) break;
        __syncthreads();
        if (c + 2 < NC) { issue(c + 2, c & 1); CP_COMMIT(); CP_WAIT1(); }
        else            { CP_WAIT0(); }
        __syncthreads();
    }

    const int lr4 = lane >> 2;
    const int lc2 = (lane & 3) * 2;

    #pragma unroll
    for (int mt = 0; mt < MT; mt++)
        #pragma unroll
        for (int half = 0; half < 2; half++) {
            int row = bm + warp_m0 + mt * 16 + lr4 + half * 8;
            #pragma unroll
            for (int nt = 0; nt < 4; nt++) {
                int col = bn + warp_n0 + nt * 8 + lc2;
                float v0 = acc[mt][nt][half * 2 + 0];
                float v1 = acc[mt][nt][half * 2 + 1];
                if (WHICH == 0) {
                    float2 bv = *(const float2*)&bias[col];
                    v0 = fmaxf(v0 + bv.x, 0.f);
                    v1 = fmaxf(v1 + bv.y, 0.f);
                    size_t o = (size_t)row * N + col;
                    __nv_bfloat16 h0, l0, h1, l1;
                    split_bf16(v0, h0, l0); split_bf16(v1, h1, l1);
                    *(__nv_bfloat162*)&g_hidH[o] = {h0, h1};
                    *(__nv_bfloat162*)&g_hidL[o] = {l0, l1};
                } else {
                    size_t o = (size_t)blockIdx.z * BD + (size_t)row * N + col;
                    *(float2*)&pout[o] = make_float2(v0, v1);
                }
            }
        }
}

// ---------------------------------------------------------------------------
// Fused split-K combine + VQ + epilogue (2048 blocks x 128 thr). Per row:
//   0. u = ((p0+p1)+(p2+p3)) + b2 (fp32); write out_ue.
//   1. |u|; bound scan over smem-cached (cnorm,|c|): keep j with
//      cnorm_j - 2|u||c_j| <= min_k(cnorm_k + 2|u||c_k|) + margin.
//      (Cauchy-Schwarz: true argmin always kept.)
//   2. warp-parallel exact fp32 dots (4 candidates in flight); block argmin
//      by (score, j) -> deterministic, smaller-j tie-break.
//   3. q/quant/pos/neg outputs + diff partial; last block reduces diff.
// ---------------------------------------------------------------------------
__global__ void __launch_bounds__(128) vq_epilogue_kernel(
    const float* __restrict__ codebook, const float* __restrict__ item_embed,
    const int* __restrict__ pos, const int* __restrict__ neg,
    const float* __restrict__ b2,
    float* __restrict__ out_q, float* __restrict__ out_pos,
    float* __restrict__ out_neg, float* __restrict__ out_diff,
    float* __restrict__ out_ue)
{
    __shared__ float  su[DD];         // u row (2 KB)
    __shared__ float2 scn[CBK];       // cached (cnorm,|c|) table (16 KB)
    __shared__ int    cand[CBK];      // candidate list (8 KB; worst case all)
    __shared__ float  red[4];
    __shared__ float  wbv[4];
    __shared__ int    wbj[4];
    __shared__ int    s_cnt, s_id;
    __shared__ bool   s_last;

    const int b = blockIdx.x;
    const int t = threadIdx.x;
    const int lane = t & 31;
    const int wid = t >> 5;

    // issue independent loads early (latency overlaps the work below)
    const int pp = pos[b], nn = neg[b];
    const float4 pv4 = ((const float4*)item_embed)[(size_t)pp * 128 + t];
    const float4 nv4 = ((const float4*)item_embed)[(size_t)nn * 128 + t];

    // split-K combine: u = ((p0+p1)+(p2+p3)) + bias
    float4 p0 = ((const float4*)g_part)[(size_t)b * 128 + t];
    float4 p1 = ((const float4*)(g_part + BD))[(size_t)b * 128 + t];
    float4 p2 = ((const float4*)(g_part + 2 * (size_t)BD))[(size_t)b * 128 + t];
    float4 p3 = ((const float4*)(g_part + 3 * (size_t)BD))[(size_t)b * 128 + t];
    float4 bb = ((const float4*)b2)[t];
    float4 u4 = make_float4(((p0.x + p1.x) + (p2.x + p3.x)) + bb.x,
                            ((p0.y + p1.y) + (p2.y + p3.y)) + bb.y,
                            ((p0.z + p1.z) + (p2.z + p3.z)) + bb.z,
                            ((p0.w + p1.w) + (p2.w + p3.w)) + bb.w);
    ((float4*)su)[t] = u4;
    {   // user_embed output (destination only 4B-aligned)
        size_t o = (size_t)b * DD + t * 4;
        out_ue[o + 0] = u4.x; out_ue[o + 1] = u4.y;
        out_ue[o + 2] = u4.z; out_ue[o + 3] = u4.w;
    }

    float p = u4.x * u4.x + u4.y * u4.y + u4.z * u4.z + u4.w * u4.w;
    #pragma unroll
    for (int o = 16; o > 0; o >>= 1) p += __shfl_down_sync(0xffffffffu, p, o);
    if ((t & 31) == 0) red[t >> 5] = p;
    if (t == 0) s_cnt = 0;
    __syncthreads();
    const float tu = 2.0f * sqrtf(red[0] + red[1] + red[2] + red[3]);

    // pass 1: cache table to smem + U = min_j (cnorm_j + tu*|c_j|)
    float locU = 3.0e38f;
    for (int j = t; j < CBK; j += 128) {
        float2 c2 = g_cn2[j];
        scn[j] = c2;
        locU = fminf(locU, fmaf(tu, c2.y, c2.x));
    }
    #pragma unroll
    for (int o = 16; o > 0; o >>= 1)
        locU = fminf(locU, __shfl_down_sync(0xffffffffu, locU, o));
    if ((t & 31) == 0) red[t >> 5] = locU;
    __syncthreads();
    const float U = fminf(fminf(red[0], red[1]), fminf(red[2], red[3])) + 1e-2f;

    // pass 2 (from smem): collect candidates with lower bound <= U
    for (int j = t; j < CBK; j += 128) {
        float2 c2 = scn[j];
        if (fmaf(-tu, c2.y, c2.x) <= U)
            cand[atomicAdd(&s_cnt, 1)] = j;
    }
    __syncthreads();
    const int ncand = s_cnt;

    // warp-parallel exact fp32 dots; per-warp argmin, then block argmin.
    float best = 3.0e38f;
    int   bid  = 0x7fffffff;
    for (int i = wid; i < ncand; i += 4) {
        int j = cand[i];
        const float4* crow = (const float4*)(codebook + (size_t)j * DD);
        float d = 0.f;
        #pragma unroll
        for (int e = 0; e < 4; e++) {
            float4 c4 = crow[lane + e * 32];
            float4 uu = ((const float4*)su)[lane + e * 32];
            d += c4.x * uu.x + c4.y * uu.y + c4.z * uu.z + c4.w * uu.w;
        }
        #pragma unroll
        for (int o = 16; o > 0; o >>= 1) d += __shfl_xor_sync(0xffffffffu, d, o);
        float s = scn[j].x - 2.0f * d;     // same value in all lanes
        if (s < best || (s == best && j < bid)) { best = s; bid = j; }
    }
    if (lane == 0) { wbv[wid] = best; wbj[wid] = bid; }
    __syncthreads();
    if (t == 0) {
        float bv = wbv[0]; int bj = wbj[0];
        #pragma unroll
        for (int wq = 1; wq < 4; wq++) {
            float v = wbv[wq]; int jq = wbj[wq];
            if (v < bv || (v == bv && jq < bj)) { bv = v; bj = jq; }
        }
        s_id = bj;
    }
    __syncthreads();
    const int id = s_id;

    // outputs
    float4 q = ((const float4*)codebook)[(size_t)id * 128 + t];
    float4 u = ((const float4*)su)[t];
    float4 d = make_float4(q.x - u.x, q.y - u.y, q.z - u.z, q.w - u.w);
    float4 qu = make_float4(u.x + d.x, u.y + d.y, u.z + d.z, u.w + d.w);
    ((float4*)out_q)[(size_t)b * 128 + t] = qu;
    ((float4*)out_pos)[(size_t)b * 128 + t] = pv4;
    ((float4*)out_neg)[(size_t)b * 128 + t] = nv4;

    float ds = d.x * d.x + d.y * d.y + d.z * d.z + d.w * d.w;
    #pragma unroll
    for (int o = 16; o > 0; o >>= 1) ds += __shfl_down_sync(0xffffffffu, ds, o);
    __syncthreads();
    if ((t & 31) == 0) red[t >> 5] = ds;
    __syncthreads();
    if (t == 0) {
        g_bsum[b] = red[0] + red[1] + red[2] + red[3];
        __threadfence();
        int c = atomicAdd(&g_count, 1);
        s_last = (c == BB - 1);
    }
    __syncthreads();

    if (s_last) {
        __threadfence();
        float s = 0.f;
        #pragma unroll
        for (int i = 0; i < BB / 128; i++) s += g_bsum[t + i * 128];
        __shared__ float sv[128];
        sv[t] = s;
        __syncthreads();
        for (int o = 64; o > 0; o >>= 1) {
            if (t < o) sv[t] += sv[t + o];
            __syncthreads();
        }
        if (t == 0) {
            *out_diff = sv[0] * (1.0f / (float)BD);
            g_count = 0;                       // reset for next graph replay
        }
    }
}

// ---------------------------------------------------------------------------
extern "C" void kernel_launch(void* const* d_in, const int* in_sizes, int n_in,
                              void* d_out, int out_size)
{
    const int*   items      = (const int*)  d_in[1];
    const int*   pos        = (const int*)  d_in[2];
    const int*   neg        = (const int*)  d_in[3];
    const float* item_embed = (const float*)d_in[4];
    const float* W1         = (const float*)d_in[5];
    const float* b1         = (const float*)d_in[6];
    const float* W2         = (const float*)d_in[7];
    const float* b2         = (const float*)d_in[8];
    const float* codebook   = (const float*)d_in[9];

    float* out      = (float*)d_out;
    float* out_q    = out;
    float* out_pos  = out + (size_t)BD;
    float* out_neg  = out + (size_t)2 * BD;
    float* out_diff = out + (size_t)3 * BD;
    float* out_ue   = out + (size_t)3 * BD + 1;

    const int SMEM_G = 2 * 2 * (128 + 64) * 128;   // 98304 (2 stages)
    cudaFuncSetAttribute((const void*)gemm_mma<128, 0>,
                         cudaFuncAttributeMaxDynamicSharedMemorySize, SMEM_G);
    cudaFuncSetAttribute((const void*)gemm_mma<128, 1>,
                         cudaFuncAttributeMaxDynamicSharedMemorySize, SMEM_G);

    __nv_bfloat16 *meanH, *meanL, *hidH, *hidL, *w1tH, *w1tL, *w2tH, *w2tL;
    float* partp;
    cudaGetSymbolAddress((void**)&meanH, g_meanH);
    cudaGetSymbolAddress((void**)&meanL, g_meanL);
    cudaGetSymbolAddress((void**)&hidH,  g_hidH);
    cudaGetSymbolAddress((void**)&hidL,  g_hidL);
    cudaGetSymbolAddress((void**)&w1tH,  g_W1tH);
    cudaGetSymbolAddress((void**)&w1tL,  g_W1tL);
    cudaGetSymbolAddress((void**)&w2tH,  g_W2tH);
    cudaGetSymbolAddress((void**)&w2tL,  g_W2tL);
    cudaGetSymbolAddress((void**)&partp, g_part);

    // two-pass gather (L2-resident item ranges) + misc prep
    prepA_kernel<<<5120, 128>>>(items, item_embed, codebook, W1, W2);
    prepB_kernel<<<2048, 128>>>(items, item_embed);

    // gemm0: full-K, grid 256 -> 2 CTAs/SM, compute-bound
    gemm_mma<128, 0><<<dim3(HHID / 64, BB / 128, 1), 256, SMEM_G>>>(
        meanH, meanL, w1tH, w1tL, b1, nullptr, HHID, DD, DD);
    // gemm1: split-K (SPLK slices of K=1024), grid 512
    gemm_mma<128, 1><<<dim3(DD / 64, BB / 128, SPLK), 256, SMEM_G>>>(
        hidH, hidL, w2tH, w2tL, nullptr, partp, DD, HHID / SPLK, HHID);

    vq_epilogue_kernel<<<BB, 128>>>(codebook, item_embed, pos, neg, b2,
                                    out_q, out_pos, out_neg, out_diff, out_ue);
}